// round 9
// baseline (speedup 1.0000x reference)
#include <cuda_runtime.h>
#include <math.h>

#define NN 50000
#define DD 64
#define EE 1250000
#define BB 4096
#define ROW4 16              // float4 per embedding row

typedef unsigned long long u64;

// ---------------- scratch (device globals; no allocation) ----------------
__device__ float g_embA[NN * DD];
__device__ float g_embB[NN * DD];
__device__ float g_agg [NN * DD];
__device__ float g_ue[BB * 256];
__device__ float g_pe[BB * 256];
__device__ float g_ne[BB * 256];

// ---------------- packed fp32x2 helpers (Blackwell) ----------------
__device__ __forceinline__ u64 fma2(u64 a, u64 b, u64 c) {
    u64 d;
    asm("fma.rn.f32x2 %0, %1, %2, %3;" : "=l"(d) : "l"(a), "l"(b), "l"(c));
    return d;
}
__device__ __forceinline__ void unpack2(float& lo, float& hi, u64 v) {
    unsigned a, b;
    asm("mov.b64 {%0, %1}, %2;" : "=r"(a), "=r"(b) : "l"(v));
    lo = __uint_as_float(a); hi = __uint_as_float(b);
}

// ---------------- kernels ----------------

__global__ void zero_agg_kernel() {
    int i = blockIdx.x * blockDim.x + threadIdx.x;
    if (i < NN * DD / 4)
        reinterpret_cast<float4*>(g_agg)[i] = make_float4(0.f, 0.f, 0.f, 0.f);
}

// 16 threads per edge; one float4 chunk per thread; vector red scatter.
__global__ void spmm_kernel(const float* __restrict__ emb,
                            const float* __restrict__ vals,
                            const int*  __restrict__ rows,
                            const int*  __restrict__ cols) {
    unsigned gid = blockIdx.x * blockDim.x + threadIdx.x;
    unsigned e = gid >> 4;
    unsigned c = gid & 15u;
    if (e >= EE) return;
    int col = cols[e];
    int row = rows[e];
    float v = vals[e];
    float4 x = reinterpret_cast<const float4*>(emb)[(size_t)col * ROW4 + c];
    float4* dst = reinterpret_cast<float4*>(g_agg) + (size_t)row * ROW4 + c;
    asm volatile("red.global.add.v4.f32 [%0], {%1,%2,%3,%4};"
                 :: "l"(dst), "f"(v * x.x), "f"(v * x.y), "f"(v * x.z), "f"(v * x.w)
                 : "memory");
}

// ---------------- fused dense layer (uniform-W GEMM, 512 thr) ----------------
//   sx = (agg+emb) @ W1^T + b1
//   ox = agg * (emb @ W2^T + b2)
//   out = leaky_relu(sx + ox, 0.01)
// Block = 128 nodes x 64 outputs, 512 threads (16 warps).
// Warp = (node-half, j-group of 8). Thread = one node PAIR x 8 outputs.
// All W loads are warp-UNIFORM (broadcast, 1 wavefront); x/ax loads are
// natural consecutive pairs (2 wavefronts). 12 wf + 16 fma2 per warp per k.
#define BM 128
#define XS 132                                 // row stride (floats) all arrays
#define OFF_X  0
#define OFF_AX (64 * XS)                       // 8448
#define OFF_W1 (2 * 64 * XS)                   // 16896
#define OFF_W2 (3 * 64 * XS)                   // 25344
#define OFF_B1 (4 * 64 * XS)                   // 33792
#define OFF_B2 (OFF_B1 + 64)
#define DSM_FLOATS (OFF_B2 + 64)               // 33920 floats = 135680 B

__global__ void __launch_bounds__(512, 1) dense_kernel(
        const float* __restrict__ src,
        const float* __restrict__ w1,
        const float* __restrict__ b1,
        const float* __restrict__ w2,
        const float* __restrict__ b2,
        float* __restrict__ dst) {
    extern __shared__ float sm[];
    float* sX  = sm + OFF_X;
    float* sAX = sm + OFF_AX;
    float* sW1 = sm + OFF_W1;
    float* sW2 = sm + OFF_W2;
    float* sB1 = sm + OFF_B1;
    float* sB2 = sm + OFF_B2;

    const int tid = threadIdx.x;
    const int base = blockIdx.x * BM;
    const int nrows = min(BM, NN - base);

    // ---- stage W1/W2 transposed+duplicated: sW[k][2j] = sW[k][2j+1] = w[j][k]
    {
        const float4* w1v = reinterpret_cast<const float4*>(w1);
        const float4* w2v = reinterpret_cast<const float4*>(w2);
        for (int i = tid; i < DD * ROW4; i += 512) {
            int j = i >> 4, c = i & 15;
            float4 a = w1v[j * ROW4 + c];
            float4 b = w2v[j * ROW4 + c];
            int k0 = 4 * c;
            sW1[(k0 + 0) * XS + 2 * j] = a.x; sW1[(k0 + 0) * XS + 2 * j + 1] = a.x;
            sW1[(k0 + 1) * XS + 2 * j] = a.y; sW1[(k0 + 1) * XS + 2 * j + 1] = a.y;
            sW1[(k0 + 2) * XS + 2 * j] = a.z; sW1[(k0 + 2) * XS + 2 * j + 1] = a.z;
            sW1[(k0 + 3) * XS + 2 * j] = a.w; sW1[(k0 + 3) * XS + 2 * j + 1] = a.w;
            sW2[(k0 + 0) * XS + 2 * j] = b.x; sW2[(k0 + 0) * XS + 2 * j + 1] = b.x;
            sW2[(k0 + 1) * XS + 2 * j] = b.y; sW2[(k0 + 1) * XS + 2 * j + 1] = b.y;
            sW2[(k0 + 2) * XS + 2 * j] = b.z; sW2[(k0 + 2) * XS + 2 * j + 1] = b.z;
            sW2[(k0 + 3) * XS + 2 * j] = b.w; sW2[(k0 + 3) * XS + 2 * j + 1] = b.w;
        }
        if (tid < DD) { sB1[tid] = b1[tid]; sB2[tid] = b2[tid]; }
    }
    // ---- stage X / AX=X+AGG transposed [k][n] (zero-pad tail rows) ----
    {
        const float4* srcv = reinterpret_cast<const float4*>(src);
        const float4* aggv = reinterpret_cast<const float4*>(g_agg);
        for (int i = tid; i < BM * ROW4; i += 512) {
            int n = i >> 4, c = i & 15;
            float4 xv = make_float4(0.f, 0.f, 0.f, 0.f);
            float4 av = xv;
            if (n < nrows) {
                xv = srcv[(size_t)(base + n) * ROW4 + c];
                av = aggv[(size_t)(base + n) * ROW4 + c];
            }
            int k0 = 4 * c;
            sX [(k0 + 0) * XS + n] = xv.x;        sX [(k0 + 1) * XS + n] = xv.y;
            sX [(k0 + 2) * XS + n] = xv.z;        sX [(k0 + 3) * XS + n] = xv.w;
            sAX[(k0 + 0) * XS + n] = xv.x + av.x; sAX[(k0 + 1) * XS + n] = xv.y + av.y;
            sAX[(k0 + 2) * XS + n] = xv.z + av.z; sAX[(k0 + 3) * XS + n] = xv.w + av.w;
        }
    }
    __syncthreads();

    // warp mapping: nh = wid>>3 (node half), jg = wid&7 (j group of 8)
    // thread: node pair n0,n0+1 with n0 = nh*64 + lane*2; outputs j0..j0+7
    const int lane = tid & 31;
    const int wid = tid >> 5;
    const int n0 = (wid >> 3) * 64 + lane * 2;
    const int j0 = (wid & 7) * 8;

    u64 c1[8], c2[8];
#pragma unroll
    for (int p = 0; p < 8; p++) { c1[p] = 0; c2[p] = 0; }

    const float* xp  = sX  + n0;
    const float* ap  = sAX + n0;
    const float* w1p = sW1 + 2 * j0;   // warp-uniform address
    const float* w2p = sW2 + 2 * j0;

#pragma unroll 8
    for (int k = 0; k < DD; k++) {
        const int ko = k * XS;
        u64 xv = *reinterpret_cast<const u64*>(xp + ko);   // (x_n0, x_n1)
        u64 av = *reinterpret_cast<const u64*>(ap + ko);   // (ax_n0, ax_n1)
        ulonglong2 w1a = *reinterpret_cast<const ulonglong2*>(w1p + ko);       // j0,j0+1 dup'd
        ulonglong2 w1b = *reinterpret_cast<const ulonglong2*>(w1p + ko + 4);   // j0+2,3
        ulonglong2 w1c = *reinterpret_cast<const ulonglong2*>(w1p + ko + 8);   // j0+4,5
        ulonglong2 w1d = *reinterpret_cast<const ulonglong2*>(w1p + ko + 12);  // j0+6,7
        ulonglong2 w2a = *reinterpret_cast<const ulonglong2*>(w2p + ko);
        ulonglong2 w2b = *reinterpret_cast<const ulonglong2*>(w2p + ko + 4);
        ulonglong2 w2c = *reinterpret_cast<const ulonglong2*>(w2p + ko + 8);
        ulonglong2 w2d = *reinterpret_cast<const ulonglong2*>(w2p + ko + 12);

        c1[0] = fma2(av, w1a.x, c1[0]); c1[1] = fma2(av, w1a.y, c1[1]);
        c1[2] = fma2(av, w1b.x, c1[2]); c1[3] = fma2(av, w1b.y, c1[3]);
        c1[4] = fma2(av, w1c.x, c1[4]); c1[5] = fma2(av, w1c.y, c1[5]);
        c1[6] = fma2(av, w1d.x, c1[6]); c1[7] = fma2(av, w1d.y, c1[7]);
        c2[0] = fma2(xv, w2a.x, c2[0]); c2[1] = fma2(xv, w2a.y, c2[1]);
        c2[2] = fma2(xv, w2b.x, c2[2]); c2[3] = fma2(xv, w2b.y, c2[3]);
        c2[4] = fma2(xv, w2c.x, c2[4]); c2[5] = fma2(xv, w2c.y, c2[5]);
        c2[6] = fma2(xv, w2d.x, c2[6]); c2[7] = fma2(xv, w2d.y, c2[7]);
    }

    // ---- epilogue: bias, agg (= AX - X) elementwise, leaky-relu, store ----
    float bb1[8], bb2[8];
#pragma unroll
    for (int p = 0; p < 8; p++) { bb1[p] = sB1[j0 + p]; bb2[p] = sB2[j0 + p]; }

    float oa[8], ob[8];
#pragma unroll
    for (int p = 0; p < 8; p++) {
        float s1a, s1b, s2a, s2b;
        unpack2(s1a, s1b, c1[p]);          // node n0 / n0+1, output j0+p
        unpack2(s2a, s2b, c2[p]);
        const int jj = (j0 + p) * XS;
        u64 axp = *reinterpret_cast<const u64*>(sAX + jj + n0);
        u64 xxp = *reinterpret_cast<const u64*>(sX  + jj + n0);
        float axa, axb, xa, xb;
        unpack2(axa, axb, axp);
        unpack2(xa,  xb,  xxp);
        float aga = axa - xa;
        float agb = axb - xb;
        float va = (s1a + bb1[p]) + aga * (s2a + bb2[p]);
        float vb = (s1b + bb1[p]) + agb * (s2b + bb2[p]);
        oa[p] = va > 0.f ? va : 0.01f * va;
        ob[p] = vb > 0.f ? vb : 0.01f * vb;
    }
    if (n0 < nrows) {
        float4* d0 = reinterpret_cast<float4*>(dst + (size_t)(base + n0) * DD + j0);
        d0[0] = make_float4(oa[0], oa[1], oa[2], oa[3]);
        d0[1] = make_float4(oa[4], oa[5], oa[6], oa[7]);
        if (n0 + 1 < nrows) {
            float4* d1 = reinterpret_cast<float4*>(dst + (size_t)(base + n0 + 1) * DD + j0);
            d1[0] = make_float4(ob[0], ob[1], ob[2], ob[3]);
            d1[1] = make_float4(ob[4], ob[5], ob[6], ob[7]);
        }
    }
}

// ---------------- gather + loss ----------------

__global__ void gather_kernel(const float* __restrict__ emb,
                              const int* __restrict__ user,
                              const int* __restrict__ pos,
                              const int* __restrict__ neg,
                              int layer) {
    unsigned t = blockIdx.x * blockDim.x + threadIdx.x;
    if (t >= BB * 16) return;
    unsigned i = t >> 4;
    unsigned c = t & 15u;
    unsigned doff = i * 64 + (unsigned)layer * 16 + c;
    const float4* ev = reinterpret_cast<const float4*>(emb);
    reinterpret_cast<float4*>(g_ue)[doff] = ev[(size_t)user[i] * ROW4 + c];
    reinterpret_cast<float4*>(g_pe)[doff] = ev[(size_t)pos [i] * ROW4 + c];
    reinterpret_cast<float4*>(g_ne)[doff] = ev[(size_t)neg [i] * ROW4 + c];
}

__global__ void zero_out_kernel(float* out) {
    if (threadIdx.x == 0 && blockIdx.x == 0) out[0] = 0.f;
}

__global__ void loss_kernel(float* __restrict__ out) {
    int i = blockIdx.x * blockDim.x + threadIdx.x;
    float dp = 0.f, dn = 0.f;
    if (i < BB) {
        const float4* uv = reinterpret_cast<const float4*>(g_ue);
        const float4* pv = reinterpret_cast<const float4*>(g_pe);
        const float4* nv = reinterpret_cast<const float4*>(g_ne);
#pragma unroll 8
        for (int c = 0; c < 64; c++) {
            float4 u = uv[(size_t)i * 64 + c];
            float4 p = pv[(size_t)i * 64 + c];
            float4 q = nv[(size_t)i * 64 + c];
            dp += u.x*p.x + u.y*p.y + u.z*p.z + u.w*p.w;
            dn += u.x*q.x + u.y*q.y + u.z*q.z + u.w*q.w;
        }
    }
    float d = dp - dn;
    float l = (i < BB) ? (fmaxf(-d, 0.f) + log1pf(expf(-fabsf(d)))) : 0.f;

    __shared__ float red[256];
    red[threadIdx.x] = l;
    __syncthreads();
    for (int s = 128; s > 0; s >>= 1) {
        if (threadIdx.x < s) red[threadIdx.x] += red[threadIdx.x + s];
        __syncthreads();
    }
    if (threadIdx.x == 0) atomicAdd(out, red[0]);
}

// ---------------- launch ----------------

extern "C" void kernel_launch(void* const* d_in, const int* in_sizes, int n_in,
                              void* d_out, int out_size) {
    const float* emb  = (const float*)d_in[0];
    const float* w1w  = (const float*)d_in[1];
    const float* w1b  = (const float*)d_in[2];
    const float* w2w  = (const float*)d_in[3];
    const float* w2b  = (const float*)d_in[4];
    const float* vals = (const float*)d_in[5];
    const int*   rows = (const int*)d_in[6];
    const int*   cols = (const int*)d_in[7];
    const int*   user = (const int*)d_in[8];
    const int*   pos  = (const int*)d_in[9];
    const int*   neg  = (const int*)d_in[10];
    float* out = (float*)d_out;

    void *pA = nullptr, *pB = nullptr;
    cudaGetSymbolAddress(&pA, g_embA);
    cudaGetSymbolAddress(&pB, g_embB);
    float* eA = (float*)pA;
    float* eB = (float*)pB;

    const int SMEM_BYTES = DSM_FLOATS * 4;   // 135680
    cudaFuncSetAttribute(dense_kernel,
                         cudaFuncAttributeMaxDynamicSharedMemorySize, SMEM_BYTES);

    const int ZB = (NN * DD / 4 + 255) / 256;
    const int SB = (EE * 16) / 256;           // 78125 exact
    const int DB = (NN + BM - 1) / BM;        // 391
    const int GB = (BB * 16 + 255) / 256;

    // layer 0 input gather
    gather_kernel<<<GB, 256>>>(emb, user, pos, neg, 0);

    // layer 1: emb -> eA
    zero_agg_kernel<<<ZB, 256>>>();
    spmm_kernel<<<SB, 256>>>(emb, vals, rows, cols);
    dense_kernel<<<DB, 512, SMEM_BYTES>>>(emb, w1w, w1b, w2w, w2b, eA);
    gather_kernel<<<GB, 256>>>(eA, user, pos, neg, 1);

    // layer 2: eA -> eB
    zero_agg_kernel<<<ZB, 256>>>();
    spmm_kernel<<<SB, 256>>>(eA, vals, rows, cols);
    dense_kernel<<<DB, 512, SMEM_BYTES>>>(eA, w1w + 4096, w1b + 64, w2w + 4096, w2b + 64, eB);
    gather_kernel<<<GB, 256>>>(eB, user, pos, neg, 2);

    // layer 3: eB -> eA
    zero_agg_kernel<<<ZB, 256>>>();
    spmm_kernel<<<SB, 256>>>(eB, vals, rows, cols);
    dense_kernel<<<DB, 512, SMEM_BYTES>>>(eB, w1w + 8192, w1b + 128, w2w + 8192, w2b + 128, eA);
    gather_kernel<<<GB, 256>>>(eA, user, pos, neg, 3);

    // loss
    zero_out_kernel<<<1, 32>>>(out);
    loss_kernel<<<BB / 256, 256>>>(out);
}

// round 10
// speedup vs baseline: 1.1016x; 1.1016x over previous
#include <cuda_runtime.h>
#include <math.h>

#define NN 50000
#define DD 64
#define EE 1250000
#define BB 4096
#define ROW4 16              // float4 per embedding row

// ---------------- scratch (device globals; no allocation) ----------------
__device__ float g_embA[NN * DD];
__device__ float g_embB[NN * DD];
__device__ float g_agg [NN * DD];
__device__ float g_ue[BB * 256];
__device__ float g_pe[BB * 256];
__device__ float g_ne[BB * 256];

// ---------------- tf32 helpers ----------------
__device__ __forceinline__ unsigned f2tf(float f) {
    unsigned r;
    asm("cvt.rna.tf32.f32 %0, %1;" : "=r"(r) : "f"(f));
    return r;
}
// split fp32 into tf32 hi + tf32 lo (residual)
__device__ __forceinline__ void tfsplit(float f, unsigned& hi, unsigned& lo) {
    hi = f2tf(f);
    float r = f - __uint_as_float(hi);
    lo = f2tf(r);
}
__device__ __forceinline__ void mma_tf32(float* d, const unsigned* a,
                                         unsigned b0, unsigned b1) {
    asm volatile(
        "mma.sync.aligned.m16n8k8.row.col.f32.tf32.tf32.f32 "
        "{%0,%1,%2,%3},{%4,%5,%6,%7},{%8,%9},{%0,%1,%2,%3};"
        : "+f"(d[0]), "+f"(d[1]), "+f"(d[2]), "+f"(d[3])
        : "r"(a[0]), "r"(a[1]), "r"(a[2]), "r"(a[3]), "r"(b0), "r"(b1));
}

// ---------------- kernels ----------------

__global__ void zero_agg_kernel() {
    int i = blockIdx.x * blockDim.x + threadIdx.x;
    if (i < NN * DD / 4)
        reinterpret_cast<float4*>(g_agg)[i] = make_float4(0.f, 0.f, 0.f, 0.f);
}

// 16 threads per edge; one float4 chunk per thread; vector red scatter.
__global__ void spmm_kernel(const float* __restrict__ emb,
                            const float* __restrict__ vals,
                            const int*  __restrict__ rows,
                            const int*  __restrict__ cols) {
    unsigned gid = blockIdx.x * blockDim.x + threadIdx.x;
    unsigned e = gid >> 4;
    unsigned c = gid & 15u;
    if (e >= EE) return;
    int col = cols[e];
    int row = rows[e];
    float v = vals[e];
    float4 x = reinterpret_cast<const float4*>(emb)[(size_t)col * ROW4 + c];
    float4* dst = reinterpret_cast<float4*>(g_agg) + (size_t)row * ROW4 + c;
    asm volatile("red.global.add.v4.f32 [%0], {%1,%2,%3,%4};"
                 :: "l"(dst), "f"(v * x.x), "f"(v * x.y), "f"(v * x.z), "f"(v * x.w)
                 : "memory");
}

// ---------------- fused dense layer (tf32 tensor-core GEMM) ----------------
//   sx = (agg+emb) @ W1^T + b1
//   ox = agg * (emb @ W2^T + b2)
//   out = leaky_relu(sx + ox, 0.01)
// Block = 128 nodes x 64 outputs, 256 threads (8 warps, warp = 16 rows).
// 3-product tf32 split (hi*hi + hi*lo + lo*hi) for fp32-grade precision.
#define BM 128
#define XR 68                                  // row stride (floats)
#define OFF_X   0                              // X  [n][k]  128*68
#define OFF_AX  (BM * XR)                      // AX [n][k]  128*68
#define OFF_W1H (2 * BM * XR)                  // W1 hi [j][k] 64*68
#define OFF_W1L (OFF_W1H + DD * XR)
#define OFF_W2H (OFF_W1L + DD * XR)
#define OFF_W2L (OFF_W2H + DD * XR)
#define OFF_B1  (OFF_W2L + DD * XR)
#define OFF_B2  (OFF_B1 + DD)
#define DSM_FLOATS (OFF_B2 + DD)               // 34944 floats = 139776 B

__global__ void __launch_bounds__(256, 1) dense_kernel(
        const float* __restrict__ src,
        const float* __restrict__ w1,
        const float* __restrict__ b1,
        const float* __restrict__ w2,
        const float* __restrict__ b2,
        float* __restrict__ dst) {
    extern __shared__ float sm[];
    float* sX   = sm + OFF_X;
    float* sAX  = sm + OFF_AX;
    float* sW1h = sm + OFF_W1H;
    float* sW1l = sm + OFF_W1L;
    float* sW2h = sm + OFF_W2H;
    float* sW2l = sm + OFF_W2L;
    float* sB1  = sm + OFF_B1;
    float* sB2  = sm + OFF_B2;

    const int tid = threadIdx.x;
    const int base = blockIdx.x * BM;
    const int nrows = min(BM, NN - base);

    // ---- stage W1/W2 split hi/lo, layout [j][k] stride XR ----
    for (int idx = tid; idx < DD * DD; idx += 256) {
        int j = idx >> 6, k = idx & 63;
        unsigned h, l;
        tfsplit(w1[idx], h, l);
        sW1h[j * XR + k] = __uint_as_float(h);
        sW1l[j * XR + k] = __uint_as_float(l);
        tfsplit(w2[idx], h, l);
        sW2h[j * XR + k] = __uint_as_float(h);
        sW2l[j * XR + k] = __uint_as_float(l);
    }
    if (tid < DD) { sB1[tid] = b1[tid]; sB2[tid] = b2[tid]; }

    // ---- stage X / AX fp32, layout [n][k] stride XR (zero-pad tail) ----
    {
        const float4* srcv = reinterpret_cast<const float4*>(src);
        const float4* aggv = reinterpret_cast<const float4*>(g_agg);
        for (int idx = tid; idx < BM * ROW4; idx += 256) {
            int n = idx >> 4, c = idx & 15;
            float4 xv = make_float4(0.f, 0.f, 0.f, 0.f);
            float4 av = xv;
            if (n < nrows) {
                xv = srcv[(size_t)(base + n) * ROW4 + c];
                av = aggv[(size_t)(base + n) * ROW4 + c];
            }
            float* xr = sX  + n * XR + 4 * c;
            float* ar = sAX + n * XR + 4 * c;
            xr[0] = xv.x; xr[1] = xv.y; xr[2] = xv.z; xr[3] = xv.w;
            ar[0] = xv.x + av.x; ar[1] = xv.y + av.y;
            ar[2] = xv.z + av.z; ar[3] = xv.w + av.w;
        }
    }
    __syncthreads();

    const int wid  = tid >> 5;
    const int lane = tid & 31;
    const int g  = lane >> 2;      // group id 0..7
    const int tg = lane & 3;       // thread in group 0..3
    const int row0 = wid * 16 + g; // local rows row0, row0+8
    const int row1 = row0 + 8;

    float acc1[8][4], acc2[8][4];
#pragma unroll
    for (int jt = 0; jt < 8; jt++)
#pragma unroll
        for (int p = 0; p < 4; p++) { acc1[jt][p] = 0.f; acc2[jt][p] = 0.f; }

#pragma unroll 2
    for (int ks = 0; ks < 8; ks++) {
        const int k0 = ks * 8;
        // A fragments (m16k8, row-major): a0(row0,tg) a1(row1,tg) a2(row0,tg+4) a3(row1,tg+4)
        unsigned xh[4], xl[4], axh[4], axl[4];
        {
            float f0 = sX[row0 * XR + k0 + tg];
            float f1 = sX[row1 * XR + k0 + tg];
            float f2 = sX[row0 * XR + k0 + tg + 4];
            float f3 = sX[row1 * XR + k0 + tg + 4];
            tfsplit(f0, xh[0], xl[0]); tfsplit(f1, xh[1], xl[1]);
            tfsplit(f2, xh[2], xl[2]); tfsplit(f3, xh[3], xl[3]);
            float a0 = sAX[row0 * XR + k0 + tg];
            float a1 = sAX[row1 * XR + k0 + tg];
            float a2 = sAX[row0 * XR + k0 + tg + 4];
            float a3 = sAX[row1 * XR + k0 + tg + 4];
            tfsplit(a0, axh[0], axl[0]); tfsplit(a1, axh[1], axl[1]);
            tfsplit(a2, axh[2], axl[2]); tfsplit(a3, axh[3], axl[3]);
        }
#pragma unroll
        for (int jt = 0; jt < 8; jt++) {
            // B fragment (k8n8, col-major): b0(k0+tg, j0+g), b1(k0+tg+4, j0+g)
            const int ba = (jt * 8 + g) * XR + k0 + tg;
            unsigned w1h0 = __float_as_uint(sW1h[ba]);
            unsigned w1h1 = __float_as_uint(sW1h[ba + 4]);
            unsigned w1l0 = __float_as_uint(sW1l[ba]);
            unsigned w1l1 = __float_as_uint(sW1l[ba + 4]);
            unsigned w2h0 = __float_as_uint(sW2h[ba]);
            unsigned w2h1 = __float_as_uint(sW2h[ba + 4]);
            unsigned w2l0 = __float_as_uint(sW2l[ba]);
            unsigned w2l1 = __float_as_uint(sW2l[ba + 4]);
            mma_tf32(acc1[jt], axh, w1h0, w1h1);
            mma_tf32(acc1[jt], axh, w1l0, w1l1);
            mma_tf32(acc1[jt], axl, w1h0, w1h1);
            mma_tf32(acc2[jt], xh,  w2h0, w2h1);
            mma_tf32(acc2[jt], xh,  w2l0, w2l1);
            mma_tf32(acc2[jt], xl,  w2h0, w2h1);
        }
    }

    // ---- epilogue: agg = AX - X, bias, elementwise, leaky-relu, store ----
    // C frag: c0(row0, j), c1(row0, j+1), c2(row1, j), c3(row1, j+1), j = jt*8 + tg*2
#pragma unroll
    for (int jt = 0; jt < 8; jt++) {
        const int j = jt * 8 + tg * 2;
        float bj0 = sB1[j], bj1 = sB1[j + 1];
        float cj0 = sB2[j], cj1 = sB2[j + 1];
        // row0
        if (row0 < nrows) {
            float ag0 = sAX[row0 * XR + j]     - sX[row0 * XR + j];
            float ag1 = sAX[row0 * XR + j + 1] - sX[row0 * XR + j + 1];
            float v0 = (acc1[jt][0] + bj0) + ag0 * (acc2[jt][0] + cj0);
            float v1 = (acc1[jt][1] + bj1) + ag1 * (acc2[jt][1] + cj1);
            v0 = v0 > 0.f ? v0 : 0.01f * v0;
            v1 = v1 > 0.f ? v1 : 0.01f * v1;
            *reinterpret_cast<float2*>(dst + (size_t)(base + row0) * DD + j) =
                make_float2(v0, v1);
        }
        // row1
        if (row1 < nrows) {
            float ag0 = sAX[row1 * XR + j]     - sX[row1 * XR + j];
            float ag1 = sAX[row1 * XR + j + 1] - sX[row1 * XR + j + 1];
            float v0 = (acc1[jt][2] + bj0) + ag0 * (acc2[jt][2] + cj0);
            float v1 = (acc1[jt][3] + bj1) + ag1 * (acc2[jt][3] + cj1);
            v0 = v0 > 0.f ? v0 : 0.01f * v0;
            v1 = v1 > 0.f ? v1 : 0.01f * v1;
            *reinterpret_cast<float2*>(dst + (size_t)(base + row1) * DD + j) =
                make_float2(v0, v1);
        }
    }
}

// ---------------- gather + loss ----------------

__global__ void gather_kernel(const float* __restrict__ emb,
                              const int* __restrict__ user,
                              const int* __restrict__ pos,
                              const int* __restrict__ neg,
                              int layer) {
    unsigned t = blockIdx.x * blockDim.x + threadIdx.x;
    if (t >= BB * 16) return;
    unsigned i = t >> 4;
    unsigned c = t & 15u;
    unsigned doff = i * 64 + (unsigned)layer * 16 + c;
    const float4* ev = reinterpret_cast<const float4*>(emb);
    reinterpret_cast<float4*>(g_ue)[doff] = ev[(size_t)user[i] * ROW4 + c];
    reinterpret_cast<float4*>(g_pe)[doff] = ev[(size_t)pos [i] * ROW4 + c];
    reinterpret_cast<float4*>(g_ne)[doff] = ev[(size_t)neg [i] * ROW4 + c];
}

__global__ void zero_out_kernel(float* out) {
    if (threadIdx.x == 0 && blockIdx.x == 0) out[0] = 0.f;
}

__global__ void loss_kernel(float* __restrict__ out) {
    int i = blockIdx.x * blockDim.x + threadIdx.x;
    float dp = 0.f, dn = 0.f;
    if (i < BB) {
        const float4* uv = reinterpret_cast<const float4*>(g_ue);
        const float4* pv = reinterpret_cast<const float4*>(g_pe);
        const float4* nv = reinterpret_cast<const float4*>(g_ne);
#pragma unroll 8
        for (int c = 0; c < 64; c++) {
            float4 u = uv[(size_t)i * 64 + c];
            float4 p = pv[(size_t)i * 64 + c];
            float4 q = nv[(size_t)i * 64 + c];
            dp += u.x*p.x + u.y*p.y + u.z*p.z + u.w*p.w;
            dn += u.x*q.x + u.y*q.y + u.z*q.z + u.w*q.w;
        }
    }
    float d = dp - dn;
    float l = (i < BB) ? (fmaxf(-d, 0.f) + log1pf(expf(-fabsf(d)))) : 0.f;

    __shared__ float red[256];
    red[threadIdx.x] = l;
    __syncthreads();
    for (int s = 128; s > 0; s >>= 1) {
        if (threadIdx.x < s) red[threadIdx.x] += red[threadIdx.x + s];
        __syncthreads();
    }
    if (threadIdx.x == 0) atomicAdd(out, red[0]);
}

// ---------------- launch ----------------

extern "C" void kernel_launch(void* const* d_in, const int* in_sizes, int n_in,
                              void* d_out, int out_size) {
    const float* emb  = (const float*)d_in[0];
    const float* w1w  = (const float*)d_in[1];
    const float* w1b  = (const float*)d_in[2];
    const float* w2w  = (const float*)d_in[3];
    const float* w2b  = (const float*)d_in[4];
    const float* vals = (const float*)d_in[5];
    const int*   rows = (const int*)d_in[6];
    const int*   cols = (const int*)d_in[7];
    const int*   user = (const int*)d_in[8];
    const int*   pos  = (const int*)d_in[9];
    const int*   neg  = (const int*)d_in[10];
    float* out = (float*)d_out;

    void *pA = nullptr, *pB = nullptr;
    cudaGetSymbolAddress(&pA, g_embA);
    cudaGetSymbolAddress(&pB, g_embB);
    float* eA = (float*)pA;
    float* eB = (float*)pB;

    const int SMEM_BYTES = DSM_FLOATS * 4;   // 139776
    cudaFuncSetAttribute(dense_kernel,
                         cudaFuncAttributeMaxDynamicSharedMemorySize, SMEM_BYTES);

    const int ZB = (NN * DD / 4 + 255) / 256;
    const int SB = (EE * 16) / 256;           // 78125 exact
    const int DB = (NN + BM - 1) / BM;        // 391
    const int GB = (BB * 16 + 255) / 256;

    // layer 0 input gather
    gather_kernel<<<GB, 256>>>(emb, user, pos, neg, 0);

    // layer 1: emb -> eA
    zero_agg_kernel<<<ZB, 256>>>();
    spmm_kernel<<<SB, 256>>>(emb, vals, rows, cols);
    dense_kernel<<<DB, 256, SMEM_BYTES>>>(emb, w1w, w1b, w2w, w2b, eA);
    gather_kernel<<<GB, 256>>>(eA, user, pos, neg, 1);

    // layer 2: eA -> eB
    zero_agg_kernel<<<ZB, 256>>>();
    spmm_kernel<<<SB, 256>>>(eA, vals, rows, cols);
    dense_kernel<<<DB, 256, SMEM_BYTES>>>(eA, w1w + 4096, w1b + 64, w2w + 4096, w2b + 64, eB);
    gather_kernel<<<GB, 256>>>(eB, user, pos, neg, 2);

    // layer 3: eB -> eA
    zero_agg_kernel<<<ZB, 256>>>();
    spmm_kernel<<<SB, 256>>>(eB, vals, rows, cols);
    dense_kernel<<<DB, 256, SMEM_BYTES>>>(eB, w1w + 8192, w1b + 128, w2w + 8192, w2b + 128, eA);
    gather_kernel<<<GB, 256>>>(eA, user, pos, neg, 3);

    // loss
    zero_out_kernel<<<1, 32>>>(out);
    loss_kernel<<<BB / 256, 256>>>(out);
}